// round 16
// baseline (speedup 1.0000x reference)
#include <cuda_runtime.h>
#include <math.h>

#define Nn    50000
#define Ee    800000
#define LGEe  1600000
#define FNODE 256
#define Tt    64
#define HIDd  128
#define OUTd  64
#define SLOPE 0.2f
#define SCHUNK 4096

typedef unsigned long long u64;
typedef unsigned int u32;

// ---------------- scratch (static device globals; no allocation) ----------------
__device__ float    B_aggT[(size_t)Ee * Tt];
__device__ float    B_h1[(size_t)Ee * HIDd];
__device__ float    B_nodeH1[(size_t)Nn * HIDd];
__device__ float    B_nodeAgg1[(size_t)Nn * HIDd];
__device__ float    B_aggN[(size_t)Nn * HIDd];
__device__ float    B_aggN2[(size_t)Nn * HIDd];
__device__ float    B_lt[(size_t)Nn * HIDd];
__device__ float    B_xws[(size_t)Nn * HIDd];
__device__ float    B_xwn[(size_t)Nn * HIDd];
__device__ float    B_hn1[(size_t)Nn * HIDd];
__device__ float    B_hn2[(size_t)Nn * HIDd];
__device__ float    B_q[(size_t)Nn * HIDd];
__device__ float    B_k[(size_t)Nn * HIDd];
__device__ float    B_v[(size_t)Nn * HIDd];
__device__ float    B_attn[(size_t)Nn * HIDd];
__device__ float    B_wkp[256 * 128];   // [Weg@Weas@Wk ; Weg@Wean@Wk]
__device__ float    B_wvp[256 * 128];   // [Weg@Weas@Wv ; Weg@Wean@Wv]
__device__ float    B_wtp[256 * 128];   // [W_tsa2_s@W_etn ; W_tsa2_n@W_etn]
__device__ float    B_wtmp[128 * 128];

// CSR structures (separate scratch per concurrent build)
__device__ int LG_cnt[Ee];
__device__ int LG_cur[Ee];
__device__ int RAW_cnt[Nn];
__device__ int RAW_cur[Nn];
__device__ int HH_cnt[Nn];
__device__ int HH_cur[Nn];
__device__ int LG_rp[Ee + 1];
__device__ int LG_col[LGEe];
__device__ int RAW_rp[Nn + 1];
__device__ int RAW_col[Ee];
__device__ int H_rp[Nn + 1];
__device__ int H_col[2 * Ee];
__device__ int PART_LG[256];
__device__ int PART_RAW[256];
__device__ int PART_H[256];

__device__ __forceinline__ float apply_epi(float v, int epi) {
    if (epi == 1) return fmaxf(v, 0.f);
    if (epi == 2) return v > 0.f ? v : SLOPE * v;
    return v;
}

// ================= CSR build kernels =================
__global__ void zero_int_k(int* p, int n) {
    int t = blockIdx.x * blockDim.x + threadIdx.x;
    if (t < n) p[t] = 0;
}
__global__ void hist_k(const int* __restrict__ d, int* __restrict__ cnt, int nE) {
    int e = blockIdx.x * blockDim.x + threadIdx.x;
    if (e < nE) atomicAdd(cnt + d[e], 1);
}
__global__ void __launch_bounds__(256) chunksum_k(const int* __restrict__ cnt, int n,
                                                  int* __restrict__ part) {
    __shared__ int ws[8];
    int b = blockIdx.x, tid = threadIdx.x;
    int base = b * SCHUNK;
    int s = 0;
    for (int off = tid * 4; off < SCHUNK; off += 1024) {
        int i = base + off;
        if (i + 3 < n) { int4 c = *(const int4*)(cnt + i); s += c.x + c.y + c.z + c.w; }
        else { for (int j = 0; j < 4; j++) if (i + j < n) s += cnt[i + j]; }
    }
#pragma unroll
    for (int o = 16; o; o >>= 1) s += __shfl_xor_sync(0xffffffffu, s, o);
    if ((tid & 31) == 0) ws[tid >> 5] = s;
    __syncthreads();
    if (tid < 8) {
        int v = ws[tid];
#pragma unroll
        for (int o = 4; o; o >>= 1) v += __shfl_xor_sync(0xffu, v, o);
        if (tid == 0) part[b] = v;
    }
}
__global__ void __launch_bounds__(256) scanpart_k(int* part, int nparts, int* rp_end) {
    __shared__ int sh[256];
    int tid = threadIdx.x;
    int v = (tid < nparts) ? part[tid] : 0;
    sh[tid] = v;
    __syncthreads();
    for (int o = 1; o < 256; o <<= 1) {
        int t = (tid >= o) ? sh[tid - o] : 0;
        __syncthreads();
        sh[tid] += t;
        __syncthreads();
    }
    int incl = sh[tid];
    if (tid < nparts) part[tid] = incl - v;
    if (tid == nparts - 1) *rp_end = incl;
}
__global__ void __launch_bounds__(256) chunkscan_k(const int* __restrict__ cnt, int n,
                                                   const int* __restrict__ part,
                                                   int* __restrict__ rp,
                                                   int* __restrict__ cur) {
    __shared__ int woff[8];
    int b = blockIdx.x, tid = threadIdx.x;
    int lane = tid & 31, wid = tid >> 5;
    int base = b * SCHUNK + tid * 16;
    int v[16];
#pragma unroll
    for (int j = 0; j < 16; j += 4) {
        int i = base + j;
        int4 c = make_int4(0, 0, 0, 0);
        if (i + 3 < n) c = *(const int4*)(cnt + i);
        else {
            if (i < n) c.x = cnt[i];
            if (i + 1 < n) c.y = cnt[i + 1];
            if (i + 2 < n) c.z = cnt[i + 2];
        }
        v[j] = c.x; v[j + 1] = c.y; v[j + 2] = c.z; v[j + 3] = c.w;
    }
    int s = 0;
#pragma unroll
    for (int j = 0; j < 16; j++) { int t = v[j]; v[j] = s; s += t; }
    int incl = s;
#pragma unroll
    for (int o = 1; o < 32; o <<= 1) {
        int t = __shfl_up_sync(0xffffffffu, incl, o);
        if (lane >= o) incl += t;
    }
    int wexcl = incl - s;
    if (lane == 31) woff[wid] = incl;
    __syncthreads();
    int wbase = 0;
    for (int w = 0; w < wid; w++) wbase += woff[w];
    int offset = part[b] + wbase + wexcl;
#pragma unroll
    for (int j = 0; j < 16; j++) {
        int i = base + j;
        if (i < n) { int o = offset + v[j]; rp[i] = o; cur[i] = o; }
    }
}

__global__ void fill_src_k(const int* __restrict__ dst, const int* __restrict__ src,
                           int* __restrict__ cur, int* __restrict__ col, int nE) {
    int e = blockIdx.x * blockDim.x + threadIdx.x;
    if (e >= nE) return;
    int p = atomicAdd(cur + dst[e], 1);
    col[p] = src[e];
}
__global__ void fill_eid2_k(const int* __restrict__ H, int* __restrict__ cur,
                            int* __restrict__ col, int nE) {
    int j = blockIdx.x * blockDim.x + threadIdx.x;
    if (j >= 2 * nE) return;
    int d = H[j];
    int e = (j < nE) ? j : j - nE;
    int p = atomicAdd(cur + d, 1);
    col[p] = e;
}

// ================= gather-based segment means =================
__global__ void gather64_k(const float* __restrict__ h, const int* __restrict__ rp,
                           const int* __restrict__ col, float* __restrict__ out, int nRows) {
    int warp = blockIdx.x * (blockDim.x >> 5) + (threadIdx.x >> 5);
    int lane = threadIdx.x & 31;
    if (warp >= nRows) return;
    int a = rp[warp], b = rp[warp + 1];
    float2 acc = make_float2(0.f, 0.f);
    for (int i = a; i < b; i++) {
        int s = __ldg(col + i);
        float2 v = *(const float2*)(h + (size_t)s * Tt + lane * 2);
        acc.x += v.x; acc.y += v.y;
    }
    float inv = __fdividef(1.f, fmaxf((float)(b - a), 1.f));
    acc.x *= inv; acc.y *= inv;
    *(float2*)(out + (size_t)warp * Tt + lane * 2) = acc;
}

// ===== node-side gather: 4-way unrolled edge loop =====
__global__ void gather128x4_k(const float* __restrict__ h, const int* __restrict__ rp,
                              const int* __restrict__ col, float* __restrict__ out,
                              const float* __restrict__ addIn, int epi, int nRows) {
    int warp = blockIdx.x * (blockDim.x >> 5) + (threadIdx.x >> 5);
    int lane = threadIdx.x & 31;
    if (warp >= nRows) return;
    int a = rp[warp], b = rp[warp + 1];
    float4 acc = make_float4(0.f, 0.f, 0.f, 0.f);
    int i = a;
    for (; i + 3 < b; i += 4) {
        int s0 = __ldg(col + i),     s1 = __ldg(col + i + 1);
        int s2 = __ldg(col + i + 2), s3 = __ldg(col + i + 3);
        float4 v0 = *(const float4*)(h + (size_t)s0 * HIDd + lane * 4);
        float4 v1 = *(const float4*)(h + (size_t)s1 * HIDd + lane * 4);
        float4 v2 = *(const float4*)(h + (size_t)s2 * HIDd + lane * 4);
        float4 v3 = *(const float4*)(h + (size_t)s3 * HIDd + lane * 4);
        acc.x += (v0.x + v1.x) + (v2.x + v3.x);
        acc.y += (v0.y + v1.y) + (v2.y + v3.y);
        acc.z += (v0.z + v1.z) + (v2.z + v3.z);
        acc.w += (v0.w + v1.w) + (v2.w + v3.w);
    }
    for (; i < b; i++) {
        int s0 = __ldg(col + i);
        float4 v0 = *(const float4*)(h + (size_t)s0 * HIDd + lane * 4);
        acc.x += v0.x; acc.y += v0.y; acc.z += v0.z; acc.w += v0.w;
    }
    float inv = __fdividef(1.f, fmaxf((float)(b - a), 1.f));
    acc.x *= inv; acc.y *= inv; acc.z *= inv; acc.w *= inv;
    if (addIn) {
        float4 w = *(const float4*)(addIn + (size_t)warp * HIDd + lane * 4);
        acc.x += w.x; acc.y += w.y; acc.z += w.z; acc.w += w.w;
    }
    if (epi == 1) {
        acc.x = fmaxf(acc.x, 0.f); acc.y = fmaxf(acc.y, 0.f);
        acc.z = fmaxf(acc.z, 0.f); acc.w = fmaxf(acc.w, 0.f);
    }
    *(float4*)(out + (size_t)warp * HIDd + lane * 4) = acc;
}

// ===== composite H gather: nodeH1 = mean_H(h1), nodeAgg1 = mean_H(mean_lg(h1)) =====
__global__ void gatherH2c_k(const float* __restrict__ h1,
                            const int* __restrict__ hrp, const int* __restrict__ hcol,
                            const int* __restrict__ lgrp, const int* __restrict__ lgcol,
                            float* __restrict__ outA, float* __restrict__ outB, int nRows) {
    int warp = blockIdx.x * (blockDim.x >> 5) + (threadIdx.x >> 5);
    int lane = threadIdx.x & 31;
    if (warp >= nRows) return;
    int a = hrp[warp], b = hrp[warp + 1];
    float4 accA = make_float4(0.f, 0.f, 0.f, 0.f);
    float4 accB = make_float4(0.f, 0.f, 0.f, 0.f);
    for (int i = a; i < b; i++) {
        int e = __ldg(hcol + i);
        float4 v = *(const float4*)(h1 + (size_t)e * HIDd + lane * 4);
        accA.x += v.x; accA.y += v.y; accA.z += v.z; accA.w += v.w;
        int la = __ldg(lgrp + e), lb = __ldg(lgrp + e + 1);
        float4 t = make_float4(0.f, 0.f, 0.f, 0.f);
        int j = la;
        for (; j + 1 < lb; j += 2) {
            int s0 = __ldg(lgcol + j), s1 = __ldg(lgcol + j + 1);
            float4 u0 = *(const float4*)(h1 + (size_t)s0 * HIDd + lane * 4);
            float4 u1 = *(const float4*)(h1 + (size_t)s1 * HIDd + lane * 4);
            t.x += u0.x + u1.x; t.y += u0.y + u1.y;
            t.z += u0.z + u1.z; t.w += u0.w + u1.w;
        }
        if (j < lb) {
            int s0 = __ldg(lgcol + j);
            float4 u0 = *(const float4*)(h1 + (size_t)s0 * HIDd + lane * 4);
            t.x += u0.x; t.y += u0.y; t.z += u0.z; t.w += u0.w;
        }
        float invl = __fdividef(1.f, fmaxf((float)(lb - la), 1.f));
        accB.x += t.x * invl; accB.y += t.y * invl;
        accB.z += t.z * invl; accB.w += t.w * invl;
    }
    float inv = __fdividef(1.f, fmaxf((float)(b - a), 1.f));
    accA.x *= inv; accA.y *= inv; accA.z *= inv; accA.w *= inv;
    accB.x *= inv; accB.y *= inv; accB.z *= inv; accB.w *= inv;
    *(float4*)(outA + (size_t)warp * HIDd + lane * 4) = accA;
    *(float4*)(outB + (size_t)warp * HIDd + lane * 4) = accB;
}

// ================= single-pass online-softmax attention =================
__global__ void attn_online_k(const float* __restrict__ q, const float* __restrict__ kk,
                              const float* __restrict__ v, const int* __restrict__ rp,
                              const int* __restrict__ col,
                              float* __restrict__ attnOut, int nRows) {
    int warp = blockIdx.x * (blockDim.x >> 5) + (threadIdx.x >> 5);
    int lane = threadIdx.x & 31;
    if (warp >= nRows) return;
    int a = rp[warp], b = rp[warp + 1];
    float4 qv = *(const float4*)(q + (size_t)warp * HIDd + lane * 4);

    float m = -INFINITY, den = 0.f;
    float4 acc = make_float4(0.f, 0.f, 0.f, 0.f);
    for (int i = a; i < b; i++) {
        int s = __ldg(col + i);
        float4 kv = *(const float4*)(kk + (size_t)s * HIDd + lane * 4);
        float4 vv = *(const float4*)(v + (size_t)s * HIDd + lane * 4);
        float p = qv.x * kv.x + qv.y * kv.y + qv.z * kv.z + qv.w * kv.w;
#pragma unroll
        for (int off = 16; off; off >>= 1) p += __shfl_xor_sync(0xffffffffu, p, off);
        p *= 0.08838834764831845f;          // 1/sqrt(128)
        p = p > 0.f ? p : SLOPE * p;        // leaky relu
        float newm = fmaxf(m, p);
        float corr = expf(m - newm);        // first iter: exp(-inf)=0
        float w = expf(p - newm);
        den = den * corr + w;
        acc.x = acc.x * corr + w * vv.x;
        acc.y = acc.y * corr + w * vv.y;
        acc.z = acc.z * corr + w * vv.z;
        acc.w = acc.w * corr + w * vv.w;
        m = newm;
    }
    float invd = 1.0f / fmaxf(den, 1e-9f);
    acc.x *= invd; acc.y *= invd; acc.z *= invd; acc.w *= invd;
    *(float4*)(attnOut + (size_t)warp * HIDd + lane * 4) = acc;
}

// ================= packed-f32x2 SGEMM, double-buffered software pipeline =================
__global__ void __launch_bounds__(256, 2) gemm_k(
    const float* __restrict__ A0, int K0, const float* __restrict__ W0,
    const float* __restrict__ A1, int K1, const float* __restrict__ W1,
    float* __restrict__ C, int M, int epi)
{
    __shared__ float As[2][16][128];
    __shared__ float Bs[2][16][128];
    const int tid = threadIdx.x;
    const int tx = tid & 15;
    const int ty = tid >> 4;
    const int bm = blockIdx.x * 128;

    const int idx0 = tid * 2, idx1 = tid * 2 + 1;
    const int arow0 = idx0 >> 2, ac0 = (idx0 & 3) * 4;
    const int arow1 = idx1 >> 2, ac1 = (idx1 & 3) * 4;
    const int wrow0 = idx0 >> 5, wc0 = (idx0 & 31) * 4;
    const int wrow1 = idx1 >> 5, wc1 = (idx1 & 31) * 4;
    const int gr0 = bm + arow0, gr1 = bm + arow1;

    const int nch = (K0 + K1) >> 4;

    auto fetch = [&](int c, float4* pa, float4* pb) {
        int kc = c * 16;
        bool first = (kc < K0);
        const float* A = first ? A0 : A1;
        const float* W = first ? W0 : W1;
        int kb = first ? kc : kc - K0;
        int lda = first ? K0 : K1;
        pa[0] = make_float4(0.f, 0.f, 0.f, 0.f);
        pa[1] = make_float4(0.f, 0.f, 0.f, 0.f);
        if (gr0 < M) pa[0] = *(const float4*)(A + (size_t)gr0 * lda + kb + ac0);
        if (gr1 < M) pa[1] = *(const float4*)(A + (size_t)gr1 * lda + kb + ac1);
        pb[0] = *(const float4*)(W + (size_t)(kb + wrow0) * 128 + wc0);
        pb[1] = *(const float4*)(W + (size_t)(kb + wrow1) * 128 + wc1);
    };
    auto stile = [&](int buf, const float4* pa, const float4* pb) {
        As[buf][ac0 + 0][arow0] = pa[0].x;
        As[buf][ac0 + 1][arow0] = pa[0].y;
        As[buf][ac0 + 2][arow0] = pa[0].z;
        As[buf][ac0 + 3][arow0] = pa[0].w;
        As[buf][ac1 + 0][arow1] = pa[1].x;
        As[buf][ac1 + 1][arow1] = pa[1].y;
        As[buf][ac1 + 2][arow1] = pa[1].z;
        As[buf][ac1 + 3][arow1] = pa[1].w;
        *(float4*)&Bs[buf][wrow0][wc0] = pb[0];
        *(float4*)&Bs[buf][wrow1][wc1] = pb[1];
    };

    u64 acc[8][4];
#pragma unroll
    for (int i = 0; i < 8; i++)
#pragma unroll
        for (int j = 0; j < 4; j++) acc[i][j] = 0ull;

    float4 pa[2], pb[2];
    fetch(0, pa, pb);
    stile(0, pa, pb);
    if (nch > 1) fetch(1, pa, pb);
    __syncthreads();

    for (int c = 0; c < nch; c++) {
        int buf = c & 1;
        if (c + 1 < nch) {
            stile(buf ^ 1, pa, pb);
            if (c + 2 < nch) fetch(c + 2, pa, pb);
        }
#pragma unroll
        for (int kk = 0; kk < 16; kk++) {
            u32 a1r[8];
            u64 a2[8], b2[4];
            *(float4*)&a1r[0] = *(const float4*)&As[buf][kk][ty * 8];
            *(float4*)&a1r[4] = *(const float4*)&As[buf][kk][ty * 8 + 4];
            *(float4*)&b2[0] = *(const float4*)&Bs[buf][kk][tx * 8 + 0];
            *(float4*)&b2[2] = *(const float4*)&Bs[buf][kk][tx * 8 + 4];
#pragma unroll
            for (int i = 0; i < 8; i++)
                asm("mov.b64 %0, {%1, %1};" : "=l"(a2[i]) : "r"(a1r[i]));
#pragma unroll
            for (int i = 0; i < 8; i++)
#pragma unroll
                for (int j = 0; j < 4; j++)
                    asm("fma.rn.f32x2 %0, %1, %2, %0;"
                        : "+l"(acc[i][j]) : "l"(a2[i]), "l"(b2[j]));
        }
        __syncthreads();
    }

#pragma unroll
    for (int i = 0; i < 8; i++) {
        int gr = bm + ty * 8 + i;
        if (gr >= M) continue;
        float o[8];
#pragma unroll
        for (int j = 0; j < 4; j++) {
            u32 lo = (u32)(acc[i][j] & 0xFFFFFFFFull);
            u32 hi = (u32)(acc[i][j] >> 32);
            o[2 * j + 0] = apply_epi(__uint_as_float(lo), epi);
            o[2 * j + 1] = apply_epi(__uint_as_float(hi), epi);
        }
        float* crow = C + (size_t)gr * 128 + tx * 8;
        *(float4*)(crow + 0) = make_float4(o[0], o[1], o[2], o[3]);
        *(float4*)(crow + 4) = make_float4(o[4], o[5], o[6], o[7]);
    }
}

// ---------------- final: logits + log_softmax ----------------
__global__ void __launch_bounds__(256) final_k(const float* __restrict__ hn2,
                                               const float* __restrict__ attn,
                                               const float* __restrict__ Wout,
                                               float* __restrict__ out) {
    __shared__ float sW[128 * 64];
    __shared__ float srow[8][128];
    int tid = threadIdx.x;
#pragma unroll
    for (int i = 0; i < 32; i++) sW[tid + i * 256] = Wout[tid + i * 256];
    __syncthreads();

    int w = tid >> 5, lane = tid & 31;
    int n = blockIdx.x * 8 + w;
    if (n >= Nn) return;

    float4 a = *(const float4*)(hn2 + (size_t)n * 128 + lane * 4);
    float4 b = *(const float4*)(attn + (size_t)n * 128 + lane * 4);
    float4 r = make_float4(a.x + b.x, a.y + b.y, a.z + b.z, a.w + b.w);
    *(float4*)&srow[w][lane * 4] = r;
    __syncwarp();

    float acc0 = 0.f, acc1 = 0.f;
#pragma unroll 8
    for (int k = 0; k < 128; k++) {
        float rv = srow[w][k];
        acc0 += rv * sW[k * 64 + lane];
        acc1 += rv * sW[k * 64 + lane + 32];
    }
    float mx = fmaxf(acc0, acc1);
#pragma unroll
    for (int off = 16; off; off >>= 1) mx = fmaxf(mx, __shfl_xor_sync(0xffffffffu, mx, off));
    float sm = expf(acc0 - mx) + expf(acc1 - mx);
#pragma unroll
    for (int off = 16; off; off >>= 1) sm += __shfl_xor_sync(0xffffffffu, sm, off);
    float ls = logf(sm);
    out[(size_t)n * 64 + lane] = acc0 - mx - ls;
    out[(size_t)n * 64 + lane + 32] = acc1 - mx - ls;
}

// ---------------- host ----------------
#define SYMADDR(p, s) do { void* _t = nullptr; cudaGetSymbolAddress(&_t, s); (p) = (decltype(p))_t; } while (0)

extern "C" void kernel_launch(void* const* d_in, const int* in_sizes, int n_in,
                              void* d_out, int out_size) {
    const float* x   = (const float*)d_in[0];
    const float* et  = (const float*)d_in[1];
    const int*   H   = (const int*)d_in[2];
    const int*   rei = (const int*)d_in[3];
    const int*   lg  = (const int*)d_in[4];
    const float* W_tsa1_s = (const float*)d_in[5];
    const float* W_tsa1_n = (const float*)d_in[6];
    const float* W_tsa2_s = (const float*)d_in[7];
    const float* W_tsa2_n = (const float*)d_in[8];
    const float* W_etn    = (const float*)d_in[9];
    const float* W_eg_lin = (const float*)d_in[10];
    const float* W_ea_s   = (const float*)d_in[11];
    const float* W_ea_n   = (const float*)d_in[12];
    const float* W_an1_s  = (const float*)d_in[13];
    const float* W_an1_n  = (const float*)d_in[14];
    const float* W_an2_s  = (const float*)d_in[15];
    const float* W_an2_n  = (const float*)d_in[16];
    const float* Wq       = (const float*)d_in[17];
    const float* Wk       = (const float*)d_in[18];
    const float* Wv       = (const float*)d_in[19];
    const float* W_out    = (const float*)d_in[20];
    float* out = (float*)d_out;

    const int* rsrc = rei,    * rdst = rei + Ee;
    const int* lsrc = lg,     * ldst = lg + LGEe;

    float *b_aggT, *b_h1, *b_nodeH1, *b_nodeAgg1, *b_aggN, *b_aggN2, *b_lt,
          *b_xws, *b_xwn, *b_hn1, *b_hn2, *b_q, *b_k, *b_v, *b_attn,
          *b_wkp, *b_wvp, *b_wtp, *b_wtmp;
    int *lg_cnt, *lg_cur, *raw_cnt, *raw_cur, *hh_cnt, *hh_cur;
    int *lg_rp, *lg_col, *raw_rp, *raw_col, *h_rp, *h_col;
    int *part_lg, *part_raw, *part_h;
    SYMADDR(b_aggT, B_aggT);       SYMADDR(b_h1, B_h1);
    SYMADDR(b_nodeH1, B_nodeH1);   SYMADDR(b_nodeAgg1, B_nodeAgg1);
    SYMADDR(b_aggN, B_aggN);       SYMADDR(b_aggN2, B_aggN2);
    SYMADDR(b_lt, B_lt);
    SYMADDR(b_xws, B_xws);         SYMADDR(b_xwn, B_xwn);
    SYMADDR(b_hn1, B_hn1);         SYMADDR(b_hn2, B_hn2);
    SYMADDR(b_q, B_q);             SYMADDR(b_k, B_k);
    SYMADDR(b_v, B_v);             SYMADDR(b_attn, B_attn);
    SYMADDR(b_wkp, B_wkp);         SYMADDR(b_wvp, B_wvp);
    SYMADDR(b_wtp, B_wtp);         SYMADDR(b_wtmp, B_wtmp);
    SYMADDR(lg_cnt, LG_cnt);       SYMADDR(lg_cur, LG_cur);
    SYMADDR(raw_cnt, RAW_cnt);     SYMADDR(raw_cur, RAW_cur);
    SYMADDR(hh_cnt, HH_cnt);       SYMADDR(hh_cur, HH_cur);
    SYMADDR(lg_rp, LG_rp);         SYMADDR(lg_col, LG_col);
    SYMADDR(raw_rp, RAW_rp);       SYMADDR(raw_col, RAW_col);
    SYMADDR(h_rp, H_rp);           SYMADDR(h_col, H_col);
    SYMADDR(part_lg, PART_LG);     SYMADDR(part_raw, PART_RAW);
    SYMADDR(part_h, PART_H);

    static cudaStream_t s1 = nullptr, s2 = nullptr;
    static cudaEvent_t evFork = nullptr, evH = nullptr, evRaw = nullptr, evQ = nullptr,
                       evW = nullptr, evWT = nullptr, evG = nullptr, evV = nullptr;
    if (s1 == nullptr) {
        cudaStreamCreateWithFlags(&s1, cudaStreamNonBlocking);
        cudaStreamCreateWithFlags(&s2, cudaStreamNonBlocking);
        cudaEventCreateWithFlags(&evFork, cudaEventDisableTiming);
        cudaEventCreateWithFlags(&evH, cudaEventDisableTiming);
        cudaEventCreateWithFlags(&evRaw, cudaEventDisableTiming);
        cudaEventCreateWithFlags(&evQ, cudaEventDisableTiming);
        cudaEventCreateWithFlags(&evW, cudaEventDisableTiming);
        cudaEventCreateWithFlags(&evWT, cudaEventDisableTiming);
        cudaEventCreateWithFlags(&evG, cudaEventDisableTiming);
        cudaEventCreateWithFlags(&evV, cudaEventDisableTiming);
    }

    const int TB = 256;
    const int gridE_gemm = (Ee + 127) / 128;
    const int gridN_gemm = (Nn + 127) / 128;
    const int gridE_row = (Ee + 7) / 8;
    const int gridN_row = (Nn + 7) / 8;
    const int npLG = (Ee + SCHUNK - 1) / SCHUNK;
    const int npN  = (Nn + SCHUNK - 1) / SCHUNK;

    // ======== fork ========
    cudaEventRecord(evFork, 0);
    cudaStreamWaitEvent(s1, evFork, 0);
    cudaStreamWaitEvent(s2, evFork, 0);

    // ======== s2: H incidence CSR, then folded-weight GEMMs (slack time) ========
    zero_int_k<<<(Nn + TB - 1) / TB, TB, 0, s2>>>(hh_cnt, Nn);
    hist_k<<<(2 * Ee + TB - 1) / TB, TB, 0, s2>>>(H, hh_cnt, 2 * Ee);
    chunksum_k<<<npN, 256, 0, s2>>>(hh_cnt, Nn, part_h);
    scanpart_k<<<1, 256, 0, s2>>>(part_h, npN, h_rp + Nn);
    chunkscan_k<<<npN, 256, 0, s2>>>(hh_cnt, Nn, part_h, h_rp, hh_cur);
    fill_eid2_k<<<(2 * Ee + TB - 1) / TB, TB, 0, s2>>>(H, hh_cur, h_col, Ee);
    cudaEventRecord(evH, s2);
    // Wtp = [W_tsa2_s@W_etn ; W_tsa2_n@W_etn]
    gemm_k<<<1, 256, 0, s2>>>(W_tsa2_s, HIDd, W_etn, nullptr, 0, nullptr, b_wtp, 128, 0);
    gemm_k<<<1, 256, 0, s2>>>(W_tsa2_n, HIDd, W_etn, nullptr, 0, nullptr, b_wtp + 128 * 128, 128, 0);
    cudaEventRecord(evWT, s2);
    // Wkp/Wvp = W_eg_lin @ (W_ea_{s,n} @ W{k,v})
    gemm_k<<<1, 256, 0, s2>>>(W_ea_s, HIDd, Wk, nullptr, 0, nullptr, b_wtmp, 128, 0);
    gemm_k<<<1, 256, 0, s2>>>(W_eg_lin, HIDd, b_wtmp, nullptr, 0, nullptr, b_wkp, 128, 0);
    gemm_k<<<1, 256, 0, s2>>>(W_ea_n, HIDd, Wk, nullptr, 0, nullptr, b_wtmp, 128, 0);
    gemm_k<<<1, 256, 0, s2>>>(W_eg_lin, HIDd, b_wtmp, nullptr, 0, nullptr, b_wkp + 128 * 128, 128, 0);
    gemm_k<<<1, 256, 0, s2>>>(W_ea_s, HIDd, Wv, nullptr, 0, nullptr, b_wtmp, 128, 0);
    gemm_k<<<1, 256, 0, s2>>>(W_eg_lin, HIDd, b_wtmp, nullptr, 0, nullptr, b_wvp, 128, 0);
    gemm_k<<<1, 256, 0, s2>>>(W_ea_n, HIDd, Wv, nullptr, 0, nullptr, b_wtmp, 128, 0);
    gemm_k<<<1, 256, 0, s2>>>(W_eg_lin, HIDd, b_wtmp, nullptr, 0, nullptr, b_wvp + 128 * 128, 128, 0);
    cudaEventRecord(evW, s2);

    // ======== s1: raw CSR + attr_node chain + q projection ========
    zero_int_k<<<(Nn + TB - 1) / TB, TB, 0, s1>>>(raw_cnt, Nn);
    hist_k<<<(Ee + TB - 1) / TB, TB, 0, s1>>>(rdst, raw_cnt, Ee);
    chunksum_k<<<npN, 256, 0, s1>>>(raw_cnt, Nn, part_raw);
    scanpart_k<<<1, 256, 0, s1>>>(part_raw, npN, raw_rp + Nn);
    chunkscan_k<<<npN, 256, 0, s1>>>(raw_cnt, Nn, part_raw, raw_rp, raw_cur);
    fill_src_k<<<(Ee + TB - 1) / TB, TB, 0, s1>>>(rdst, rsrc, raw_cur, raw_col, Ee);
    cudaEventRecord(evRaw, s1);
    gemm_k<<<gridN_gemm, 256, 0, s1>>>(x, FNODE, W_an1_s, nullptr, 0, nullptr, b_xws, Nn, 0);
    gemm_k<<<gridN_gemm, 256, 0, s1>>>(x, FNODE, W_an1_n, nullptr, 0, nullptr, b_xwn, Nn, 0);
    gather128x4_k<<<gridN_row, TB, 0, s1>>>(b_xwn, raw_rp, raw_col, b_hn1, b_xws, 1, Nn);
    gather128x4_k<<<gridN_row, TB, 0, s1>>>(b_hn1, raw_rp, raw_col, b_aggN2, nullptr, 0, Nn);
    gemm_k<<<gridN_gemm, 256, 0, s1>>>(b_hn1, HIDd, W_an2_s, b_aggN2, HIDd, W_an2_n, b_hn2, Nn, 0);
    gemm_k<<<gridN_gemm, 256, 0, s1>>>(b_hn2, HIDd, Wq, nullptr, 0, nullptr, b_q, Nn, 0);
    cudaEventRecord(evQ, s1);

    // ======== s0: line-graph CSR + TSA1 ========
    zero_int_k<<<(Ee + TB - 1) / TB, TB>>>(lg_cnt, Ee);
    hist_k<<<(LGEe + TB - 1) / TB, TB>>>(ldst, lg_cnt, LGEe);
    chunksum_k<<<npLG, 256>>>(lg_cnt, Ee, part_lg);
    scanpart_k<<<1, 256>>>(part_lg, npLG, lg_rp + Ee);
    chunkscan_k<<<npLG, 256>>>(lg_cnt, Ee, part_lg, lg_rp, lg_cur);
    fill_src_k<<<(LGEe + TB - 1) / TB, TB>>>(ldst, lsrc, lg_cur, lg_col, LGEe);

    gather64_k<<<gridE_row, TB>>>(et, lg_rp, lg_col, b_aggT, Ee);
    gemm_k<<<gridE_gemm, 256>>>(et, Tt, W_tsa1_s, b_aggT, Tt, W_tsa1_n, b_h1, Ee, 1);

    // ======== composite TSA2+EtN: nodeH1/nodeAgg1 straight from h1 ========
    cudaStreamWaitEvent(0, evH, 0);
    gatherH2c_k<<<gridN_row, TB>>>(b_h1, h_rp, h_col, lg_rp, lg_col,
                                   b_nodeH1, b_nodeAgg1, Nn);
    cudaStreamWaitEvent(0, evWT, 0);
    gemm_k<<<gridN_gemm, 256>>>(b_nodeH1, HIDd, b_wtp,
                                b_nodeAgg1, HIDd, b_wtp + 128 * 128, b_lt, Nn, 2 /*leaky*/);

    // join raw CSR; K/V from [lt, mean_raw(lt)] via triple-folded weights.
    // k on s0, v on s2 (independent).
    cudaStreamWaitEvent(0, evRaw, 0);
    cudaStreamWaitEvent(0, evW, 0);
    gather128x4_k<<<gridN_row, TB>>>(b_lt, raw_rp, raw_col, b_aggN, nullptr, 0, Nn);
    cudaEventRecord(evG, 0);
    cudaStreamWaitEvent(s2, evG, 0);
    gemm_k<<<gridN_gemm, 256, 0, s2>>>(b_lt, HIDd, b_wvp,
                                       b_aggN, HIDd, b_wvp + 128 * 128, b_v, Nn, 0);
    cudaEventRecord(evV, s2);
    gemm_k<<<gridN_gemm, 256>>>(b_lt, HIDd, b_wkp,
                                b_aggN, HIDd, b_wkp + 128 * 128, b_k, Nn, 0);

    // join q/hn2 and v, then single-pass online attention + classifier
    cudaStreamWaitEvent(0, evQ, 0);
    cudaStreamWaitEvent(0, evV, 0);
    attn_online_k<<<gridN_row, TB>>>(b_q, b_k, b_v, raw_rp, raw_col, b_attn, Nn);
    final_k<<<(Nn + 7) / 8, 256>>>(b_hn2, b_attn, W_out, out);
}

// round 17
// speedup vs baseline: 1.0153x; 1.0153x over previous
#include <cuda_runtime.h>
#include <math.h>

#define Nn    50000
#define Ee    800000
#define LGEe  1600000
#define FNODE 256
#define Tt    64
#define HIDd  128
#define OUTd  64
#define SLOPE 0.2f
#define SCHUNK 4096

typedef unsigned long long u64;
typedef unsigned int u32;

// ---------------- scratch (static device globals; no allocation) ----------------
__device__ float    B_aggT[(size_t)Ee * Tt];
__device__ float    B_h1[(size_t)Ee * HIDd];
__device__ float    B_agg1[(size_t)Ee * HIDd];
__device__ float    B_nodeH1[(size_t)Nn * HIDd];
__device__ float    B_nodeAgg1[(size_t)Nn * HIDd];
__device__ float    B_aggN[(size_t)Nn * HIDd];
__device__ float    B_aggN2[(size_t)Nn * HIDd];
__device__ float    B_lt[(size_t)Nn * HIDd];
__device__ float    B_xws[(size_t)Nn * HIDd];
__device__ float    B_xwn[(size_t)Nn * HIDd];
__device__ float    B_hn1[(size_t)Nn * HIDd];
__device__ float    B_hn2[(size_t)Nn * HIDd];
__device__ float    B_q[(size_t)Nn * HIDd];
__device__ float    B_k[(size_t)Nn * HIDd];
__device__ float    B_v[(size_t)Nn * HIDd];
__device__ float    B_attn[(size_t)Nn * HIDd];
__device__ float    B_wkp[256 * 128];   // [Weg@Weas@Wk ; Weg@Wean@Wk]
__device__ float    B_wvp[256 * 128];   // [Weg@Weas@Wv ; Weg@Wean@Wv]
__device__ float    B_wtp[256 * 128];   // [W_tsa2_s@W_etn ; W_tsa2_n@W_etn]
__device__ float    B_wtmp[128 * 128];

// CSR structures (separate scratch per concurrent build)
__device__ int LG_cnt[Ee];
__device__ int LG_cur[Ee];
__device__ int RAW_cnt[Nn];
__device__ int RAW_cur[Nn];
__device__ int HH_cnt[Nn];
__device__ int HH_cur[Nn];
__device__ int LG_rp[Ee + 1];
__device__ int LG_col[LGEe];
__device__ int RAW_rp[Nn + 1];
__device__ int RAW_col[Ee];
__device__ int H_rp[Nn + 1];
__device__ int H_col[2 * Ee];
__device__ int PART_LG[256];
__device__ int PART_RAW[256];
__device__ int PART_H[256];

__device__ __forceinline__ float apply_epi(float v, int epi) {
    if (epi == 1) return fmaxf(v, 0.f);
    if (epi == 2) return v > 0.f ? v : SLOPE * v;
    return v;
}

// ================= CSR build kernels =================
__global__ void zero_int_k(int* p, int n) {
    int t = blockIdx.x * blockDim.x + threadIdx.x;
    if (t < n) p[t] = 0;
}
__global__ void hist_k(const int* __restrict__ d, int* __restrict__ cnt, int nE) {
    int e = blockIdx.x * blockDim.x + threadIdx.x;
    if (e < nE) atomicAdd(cnt + d[e], 1);
}
__global__ void __launch_bounds__(256) chunksum_k(const int* __restrict__ cnt, int n,
                                                  int* __restrict__ part) {
    __shared__ int ws[8];
    int b = blockIdx.x, tid = threadIdx.x;
    int base = b * SCHUNK;
    int s = 0;
    for (int off = tid * 4; off < SCHUNK; off += 1024) {
        int i = base + off;
        if (i + 3 < n) { int4 c = *(const int4*)(cnt + i); s += c.x + c.y + c.z + c.w; }
        else { for (int j = 0; j < 4; j++) if (i + j < n) s += cnt[i + j]; }
    }
#pragma unroll
    for (int o = 16; o; o >>= 1) s += __shfl_xor_sync(0xffffffffu, s, o);
    if ((tid & 31) == 0) ws[tid >> 5] = s;
    __syncthreads();
    if (tid < 8) {
        int v = ws[tid];
#pragma unroll
        for (int o = 4; o; o >>= 1) v += __shfl_xor_sync(0xffu, v, o);
        if (tid == 0) part[b] = v;
    }
}
__global__ void __launch_bounds__(256) scanpart_k(int* part, int nparts, int* rp_end) {
    __shared__ int sh[256];
    int tid = threadIdx.x;
    int v = (tid < nparts) ? part[tid] : 0;
    sh[tid] = v;
    __syncthreads();
    for (int o = 1; o < 256; o <<= 1) {
        int t = (tid >= o) ? sh[tid - o] : 0;
        __syncthreads();
        sh[tid] += t;
        __syncthreads();
    }
    int incl = sh[tid];
    if (tid < nparts) part[tid] = incl - v;
    if (tid == nparts - 1) *rp_end = incl;
}
__global__ void __launch_bounds__(256) chunkscan_k(const int* __restrict__ cnt, int n,
                                                   const int* __restrict__ part,
                                                   int* __restrict__ rp,
                                                   int* __restrict__ cur) {
    __shared__ int woff[8];
    int b = blockIdx.x, tid = threadIdx.x;
    int lane = tid & 31, wid = tid >> 5;
    int base = b * SCHUNK + tid * 16;
    int v[16];
#pragma unroll
    for (int j = 0; j < 16; j += 4) {
        int i = base + j;
        int4 c = make_int4(0, 0, 0, 0);
        if (i + 3 < n) c = *(const int4*)(cnt + i);
        else {
            if (i < n) c.x = cnt[i];
            if (i + 1 < n) c.y = cnt[i + 1];
            if (i + 2 < n) c.z = cnt[i + 2];
        }
        v[j] = c.x; v[j + 1] = c.y; v[j + 2] = c.z; v[j + 3] = c.w;
    }
    int s = 0;
#pragma unroll
    for (int j = 0; j < 16; j++) { int t = v[j]; v[j] = s; s += t; }
    int incl = s;
#pragma unroll
    for (int o = 1; o < 32; o <<= 1) {
        int t = __shfl_up_sync(0xffffffffu, incl, o);
        if (lane >= o) incl += t;
    }
    int wexcl = incl - s;
    if (lane == 31) woff[wid] = incl;
    __syncthreads();
    int wbase = 0;
    for (int w = 0; w < wid; w++) wbase += woff[w];
    int offset = part[b] + wbase + wexcl;
#pragma unroll
    for (int j = 0; j < 16; j++) {
        int i = base + j;
        if (i < n) { int o = offset + v[j]; rp[i] = o; cur[i] = o; }
    }
}

__global__ void fill_src_k(const int* __restrict__ dst, const int* __restrict__ src,
                           int* __restrict__ cur, int* __restrict__ col, int nE) {
    int e = blockIdx.x * blockDim.x + threadIdx.x;
    if (e >= nE) return;
    int p = atomicAdd(cur + dst[e], 1);
    col[p] = src[e];
}
__global__ void fill_eid2_k(const int* __restrict__ H, int* __restrict__ cur,
                            int* __restrict__ col, int nE) {
    int j = blockIdx.x * blockDim.x + threadIdx.x;
    if (j >= 2 * nE) return;
    int d = H[j];
    int e = (j < nE) ? j : j - nE;
    int p = atomicAdd(cur + d, 1);
    col[p] = e;
}

// ================= gather-based segment means (E-scale: champion bodies) =================
__global__ void gather64_k(const float* __restrict__ h, const int* __restrict__ rp,
                           const int* __restrict__ col, float* __restrict__ out, int nRows) {
    int warp = blockIdx.x * (blockDim.x >> 5) + (threadIdx.x >> 5);
    int lane = threadIdx.x & 31;
    if (warp >= nRows) return;
    int a = rp[warp], b = rp[warp + 1];
    float2 acc = make_float2(0.f, 0.f);
    for (int i = a; i < b; i++) {
        int s = __ldg(col + i);
        float2 v = *(const float2*)(h + (size_t)s * Tt + lane * 2);
        acc.x += v.x; acc.y += v.y;
    }
    float inv = __fdividef(1.f, fmaxf((float)(b - a), 1.f));
    acc.x *= inv; acc.y *= inv;
    *(float2*)(out + (size_t)warp * Tt + lane * 2) = acc;
}

__global__ void gather128_k(const float* __restrict__ h, const int* __restrict__ rp,
                            const int* __restrict__ col, float* __restrict__ out,
                            const float* __restrict__ addIn, int epi, int nRows) {
    int warp = blockIdx.x * (blockDim.x >> 5) + (threadIdx.x >> 5);
    int lane = threadIdx.x & 31;
    if (warp >= nRows) return;
    int a = rp[warp], b = rp[warp + 1];
    float4 acc = make_float4(0.f, 0.f, 0.f, 0.f);
    for (int i = a; i < b; i++) {
        int s = __ldg(col + i);
        float4 v = *(const float4*)(h + (size_t)s * HIDd + lane * 4);
        acc.x += v.x; acc.y += v.y; acc.z += v.z; acc.w += v.w;
    }
    float inv = __fdividef(1.f, fmaxf((float)(b - a), 1.f));
    acc.x *= inv; acc.y *= inv; acc.z *= inv; acc.w *= inv;
    if (addIn) {
        float4 w = *(const float4*)(addIn + (size_t)warp * HIDd + lane * 4);
        acc.x += w.x; acc.y += w.y; acc.z += w.z; acc.w += w.w;
    }
    if (epi == 1) {
        acc.x = fmaxf(acc.x, 0.f); acc.y = fmaxf(acc.y, 0.f);
        acc.z = fmaxf(acc.z, 0.f); acc.w = fmaxf(acc.w, 0.f);
    }
    *(float4*)(out + (size_t)warp * HIDd + lane * 4) = acc;
}

// ===== node-side gather: 4-way unrolled edge loop (deg ~16-32) =====
__global__ void gather128x4_k(const float* __restrict__ h, const int* __restrict__ rp,
                              const int* __restrict__ col, float* __restrict__ out,
                              const float* __restrict__ addIn, int epi, int nRows) {
    int warp = blockIdx.x * (blockDim.x >> 5) + (threadIdx.x >> 5);
    int lane = threadIdx.x & 31;
    if (warp >= nRows) return;
    int a = rp[warp], b = rp[warp + 1];
    float4 acc = make_float4(0.f, 0.f, 0.f, 0.f);
    int i = a;
    for (; i + 3 < b; i += 4) {
        int s0 = __ldg(col + i),     s1 = __ldg(col + i + 1);
        int s2 = __ldg(col + i + 2), s3 = __ldg(col + i + 3);
        float4 v0 = *(const float4*)(h + (size_t)s0 * HIDd + lane * 4);
        float4 v1 = *(const float4*)(h + (size_t)s1 * HIDd + lane * 4);
        float4 v2 = *(const float4*)(h + (size_t)s2 * HIDd + lane * 4);
        float4 v3 = *(const float4*)(h + (size_t)s3 * HIDd + lane * 4);
        acc.x += (v0.x + v1.x) + (v2.x + v3.x);
        acc.y += (v0.y + v1.y) + (v2.y + v3.y);
        acc.z += (v0.z + v1.z) + (v2.z + v3.z);
        acc.w += (v0.w + v1.w) + (v2.w + v3.w);
    }
    for (; i < b; i++) {
        int s0 = __ldg(col + i);
        float4 v0 = *(const float4*)(h + (size_t)s0 * HIDd + lane * 4);
        acc.x += v0.x; acc.y += v0.y; acc.z += v0.z; acc.w += v0.w;
    }
    float inv = __fdividef(1.f, fmaxf((float)(b - a), 1.f));
    acc.x *= inv; acc.y *= inv; acc.z *= inv; acc.w *= inv;
    if (addIn) {
        float4 w = *(const float4*)(addIn + (size_t)warp * HIDd + lane * 4);
        acc.x += w.x; acc.y += w.y; acc.z += w.z; acc.w += w.w;
    }
    if (epi == 1) {
        acc.x = fmaxf(acc.x, 0.f); acc.y = fmaxf(acc.y, 0.f);
        acc.z = fmaxf(acc.z, 0.f); acc.w = fmaxf(acc.w, 0.f);
    }
    *(float4*)(out + (size_t)warp * HIDd + lane * 4) = acc;
}

// ===== dual-source H gather: nodeH1 = mean_H(h1), nodeAgg1 = mean_H(agg1) =====
__global__ void gatherH2_k(const float* __restrict__ h1, const float* __restrict__ agg1,
                           const int* __restrict__ rp, const int* __restrict__ col,
                           float* __restrict__ outA, float* __restrict__ outB, int nRows) {
    int warp = blockIdx.x * (blockDim.x >> 5) + (threadIdx.x >> 5);
    int lane = threadIdx.x & 31;
    if (warp >= nRows) return;
    int a = rp[warp], b = rp[warp + 1];
    float4 accA = make_float4(0.f, 0.f, 0.f, 0.f);
    float4 accB = make_float4(0.f, 0.f, 0.f, 0.f);
    int i = a;
    for (; i + 1 < b; i += 2) {
        int e0 = __ldg(col + i), e1 = __ldg(col + i + 1);
        float4 a0 = *(const float4*)(h1 + (size_t)e0 * HIDd + lane * 4);
        float4 a1 = *(const float4*)(h1 + (size_t)e1 * HIDd + lane * 4);
        float4 b0 = *(const float4*)(agg1 + (size_t)e0 * HIDd + lane * 4);
        float4 b1 = *(const float4*)(agg1 + (size_t)e1 * HIDd + lane * 4);
        accA.x += a0.x + a1.x; accA.y += a0.y + a1.y;
        accA.z += a0.z + a1.z; accA.w += a0.w + a1.w;
        accB.x += b0.x + b1.x; accB.y += b0.y + b1.y;
        accB.z += b0.z + b1.z; accB.w += b0.w + b1.w;
    }
    if (i < b) {
        int e0 = __ldg(col + i);
        float4 a0 = *(const float4*)(h1 + (size_t)e0 * HIDd + lane * 4);
        float4 b0 = *(const float4*)(agg1 + (size_t)e0 * HIDd + lane * 4);
        accA.x += a0.x; accA.y += a0.y; accA.z += a0.z; accA.w += a0.w;
        accB.x += b0.x; accB.y += b0.y; accB.z += b0.z; accB.w += b0.w;
    }
    float inv = __fdividef(1.f, fmaxf((float)(b - a), 1.f));
    accA.x *= inv; accA.y *= inv; accA.z *= inv; accA.w *= inv;
    accB.x *= inv; accB.y *= inv; accB.z *= inv; accB.w *= inv;
    *(float4*)(outA + (size_t)warp * HIDd + lane * 4) = accA;
    *(float4*)(outB + (size_t)warp * HIDd + lane * 4) = accB;
}

// ================= single-pass online-softmax attention =================
__global__ void attn_online_k(const float* __restrict__ q, const float* __restrict__ kk,
                              const float* __restrict__ v, const int* __restrict__ rp,
                              const int* __restrict__ col,
                              float* __restrict__ attnOut, int nRows) {
    int warp = blockIdx.x * (blockDim.x >> 5) + (threadIdx.x >> 5);
    int lane = threadIdx.x & 31;
    if (warp >= nRows) return;
    int a = rp[warp], b = rp[warp + 1];
    float4 qv = *(const float4*)(q + (size_t)warp * HIDd + lane * 4);

    float m = -INFINITY, den = 0.f;
    float4 acc = make_float4(0.f, 0.f, 0.f, 0.f);
    for (int i = a; i < b; i++) {
        int s = __ldg(col + i);
        float4 kv = *(const float4*)(kk + (size_t)s * HIDd + lane * 4);
        float4 vv = *(const float4*)(v + (size_t)s * HIDd + lane * 4);
        float p = qv.x * kv.x + qv.y * kv.y + qv.z * kv.z + qv.w * kv.w;
#pragma unroll
        for (int off = 16; off; off >>= 1) p += __shfl_xor_sync(0xffffffffu, p, off);
        p *= 0.08838834764831845f;          // 1/sqrt(128)
        p = p > 0.f ? p : SLOPE * p;        // leaky relu
        float newm = fmaxf(m, p);
        float corr = expf(m - newm);        // first iter: exp(-inf)=0
        float w = expf(p - newm);
        den = den * corr + w;
        acc.x = acc.x * corr + w * vv.x;
        acc.y = acc.y * corr + w * vv.y;
        acc.z = acc.z * corr + w * vv.z;
        acc.w = acc.w * corr + w * vv.w;
        m = newm;
    }
    float invd = 1.0f / fmaxf(den, 1e-9f);
    acc.x *= invd; acc.y *= invd; acc.z *= invd; acc.w *= invd;
    *(float4*)(attnOut + (size_t)warp * HIDd + lane * 4) = acc;
}

// ================= packed-f32x2 SGEMM, double-buffered software pipeline =================
__global__ void __launch_bounds__(256, 2) gemm_k(
    const float* __restrict__ A0, int K0, const float* __restrict__ W0,
    const float* __restrict__ A1, int K1, const float* __restrict__ W1,
    float* __restrict__ C, int M, int epi)
{
    __shared__ float As[2][16][128];
    __shared__ float Bs[2][16][128];
    const int tid = threadIdx.x;
    const int tx = tid & 15;
    const int ty = tid >> 4;
    const int bm = blockIdx.x * 128;

    const int idx0 = tid * 2, idx1 = tid * 2 + 1;
    const int arow0 = idx0 >> 2, ac0 = (idx0 & 3) * 4;
    const int arow1 = idx1 >> 2, ac1 = (idx1 & 3) * 4;
    const int wrow0 = idx0 >> 5, wc0 = (idx0 & 31) * 4;
    const int wrow1 = idx1 >> 5, wc1 = (idx1 & 31) * 4;
    const int gr0 = bm + arow0, gr1 = bm + arow1;

    const int nch = (K0 + K1) >> 4;

    auto fetch = [&](int c, float4* pa, float4* pb) {
        int kc = c * 16;
        bool first = (kc < K0);
        const float* A = first ? A0 : A1;
        const float* W = first ? W0 : W1;
        int kb = first ? kc : kc - K0;
        int lda = first ? K0 : K1;
        pa[0] = make_float4(0.f, 0.f, 0.f, 0.f);
        pa[1] = make_float4(0.f, 0.f, 0.f, 0.f);
        if (gr0 < M) pa[0] = *(const float4*)(A + (size_t)gr0 * lda + kb + ac0);
        if (gr1 < M) pa[1] = *(const float4*)(A + (size_t)gr1 * lda + kb + ac1);
        pb[0] = *(const float4*)(W + (size_t)(kb + wrow0) * 128 + wc0);
        pb[1] = *(const float4*)(W + (size_t)(kb + wrow1) * 128 + wc1);
    };
    auto stile = [&](int buf, const float4* pa, const float4* pb) {
        As[buf][ac0 + 0][arow0] = pa[0].x;
        As[buf][ac0 + 1][arow0] = pa[0].y;
        As[buf][ac0 + 2][arow0] = pa[0].z;
        As[buf][ac0 + 3][arow0] = pa[0].w;
        As[buf][ac1 + 0][arow1] = pa[1].x;
        As[buf][ac1 + 1][arow1] = pa[1].y;
        As[buf][ac1 + 2][arow1] = pa[1].z;
        As[buf][ac1 + 3][arow1] = pa[1].w;
        *(float4*)&Bs[buf][wrow0][wc0] = pb[0];
        *(float4*)&Bs[buf][wrow1][wc1] = pb[1];
    };

    u64 acc[8][4];
#pragma unroll
    for (int i = 0; i < 8; i++)
#pragma unroll
        for (int j = 0; j < 4; j++) acc[i][j] = 0ull;

    float4 pa[2], pb[2];
    fetch(0, pa, pb);
    stile(0, pa, pb);
    if (nch > 1) fetch(1, pa, pb);
    __syncthreads();

    for (int c = 0; c < nch; c++) {
        int buf = c & 1;
        if (c + 1 < nch) {
            stile(buf ^ 1, pa, pb);
            if (c + 2 < nch) fetch(c + 2, pa, pb);
        }
#pragma unroll
        for (int kk = 0; kk < 16; kk++) {
            u32 a1r[8];
            u64 a2[8], b2[4];
            *(float4*)&a1r[0] = *(const float4*)&As[buf][kk][ty * 8];
            *(float4*)&a1r[4] = *(const float4*)&As[buf][kk][ty * 8 + 4];
            *(float4*)&b2[0] = *(const float4*)&Bs[buf][kk][tx * 8 + 0];
            *(float4*)&b2[2] = *(const float4*)&Bs[buf][kk][tx * 8 + 4];
#pragma unroll
            for (int i = 0; i < 8; i++)
                asm("mov.b64 %0, {%1, %1};" : "=l"(a2[i]) : "r"(a1r[i]));
#pragma unroll
            for (int i = 0; i < 8; i++)
#pragma unroll
                for (int j = 0; j < 4; j++)
                    asm("fma.rn.f32x2 %0, %1, %2, %0;"
                        : "+l"(acc[i][j]) : "l"(a2[i]), "l"(b2[j]));
        }
        __syncthreads();
    }

#pragma unroll
    for (int i = 0; i < 8; i++) {
        int gr = bm + ty * 8 + i;
        if (gr >= M) continue;
        float o[8];
#pragma unroll
        for (int j = 0; j < 4; j++) {
            u32 lo = (u32)(acc[i][j] & 0xFFFFFFFFull);
            u32 hi = (u32)(acc[i][j] >> 32);
            o[2 * j + 0] = apply_epi(__uint_as_float(lo), epi);
            o[2 * j + 1] = apply_epi(__uint_as_float(hi), epi);
        }
        float* crow = C + (size_t)gr * 128 + tx * 8;
        *(float4*)(crow + 0) = make_float4(o[0], o[1], o[2], o[3]);
        *(float4*)(crow + 4) = make_float4(o[4], o[5], o[6], o[7]);
    }
}

// ---------------- final: logits + log_softmax ----------------
__global__ void __launch_bounds__(256) final_k(const float* __restrict__ hn2,
                                               const float* __restrict__ attn,
                                               const float* __restrict__ Wout,
                                               float* __restrict__ out) {
    __shared__ float sW[128 * 64];
    __shared__ float srow[8][128];
    int tid = threadIdx.x;
#pragma unroll
    for (int i = 0; i < 32; i++) sW[tid + i * 256] = Wout[tid + i * 256];
    __syncthreads();

    int w = tid >> 5, lane = tid & 31;
    int n = blockIdx.x * 8 + w;
    if (n >= Nn) return;

    float4 a = *(const float4*)(hn2 + (size_t)n * 128 + lane * 4);
    float4 b = *(const float4*)(attn + (size_t)n * 128 + lane * 4);
    float4 r = make_float4(a.x + b.x, a.y + b.y, a.z + b.z, a.w + b.w);
    *(float4*)&srow[w][lane * 4] = r;
    __syncwarp();

    float acc0 = 0.f, acc1 = 0.f;
#pragma unroll 8
    for (int k = 0; k < 128; k++) {
        float rv = srow[w][k];
        acc0 += rv * sW[k * 64 + lane];
        acc1 += rv * sW[k * 64 + lane + 32];
    }
    float mx = fmaxf(acc0, acc1);
#pragma unroll
    for (int off = 16; off; off >>= 1) mx = fmaxf(mx, __shfl_xor_sync(0xffffffffu, mx, off));
    float sm = expf(acc0 - mx) + expf(acc1 - mx);
#pragma unroll
    for (int off = 16; off; off >>= 1) sm += __shfl_xor_sync(0xffffffffu, sm, off);
    float ls = logf(sm);
    out[(size_t)n * 64 + lane] = acc0 - mx - ls;
    out[(size_t)n * 64 + lane + 32] = acc1 - mx - ls;
}

// ---------------- host ----------------
#define SYMADDR(p, s) do { void* _t = nullptr; cudaGetSymbolAddress(&_t, s); (p) = (decltype(p))_t; } while (0)

extern "C" void kernel_launch(void* const* d_in, const int* in_sizes, int n_in,
                              void* d_out, int out_size) {
    const float* x   = (const float*)d_in[0];
    const float* et  = (const float*)d_in[1];
    const int*   H   = (const int*)d_in[2];
    const int*   rei = (const int*)d_in[3];
    const int*   lg  = (const int*)d_in[4];
    const float* W_tsa1_s = (const float*)d_in[5];
    const float* W_tsa1_n = (const float*)d_in[6];
    const float* W_tsa2_s = (const float*)d_in[7];
    const float* W_tsa2_n = (const float*)d_in[8];
    const float* W_etn    = (const float*)d_in[9];
    const float* W_eg_lin = (const float*)d_in[10];
    const float* W_ea_s   = (const float*)d_in[11];
    const float* W_ea_n   = (const float*)d_in[12];
    const float* W_an1_s  = (const float*)d_in[13];
    const float* W_an1_n  = (const float*)d_in[14];
    const float* W_an2_s  = (const float*)d_in[15];
    const float* W_an2_n  = (const float*)d_in[16];
    const float* Wq       = (const float*)d_in[17];
    const float* Wk       = (const float*)d_in[18];
    const float* Wv       = (const float*)d_in[19];
    const float* W_out    = (const float*)d_in[20];
    float* out = (float*)d_out;

    const int* rsrc = rei,    * rdst = rei + Ee;
    const int* lsrc = lg,     * ldst = lg + LGEe;

    float *b_aggT, *b_h1, *b_agg1, *b_nodeH1, *b_nodeAgg1, *b_aggN, *b_aggN2, *b_lt,
          *b_xws, *b_xwn, *b_hn1, *b_hn2, *b_q, *b_k, *b_v, *b_attn,
          *b_wkp, *b_wvp, *b_wtp, *b_wtmp;
    int *lg_cnt, *lg_cur, *raw_cnt, *raw_cur, *hh_cnt, *hh_cur;
    int *lg_rp, *lg_col, *raw_rp, *raw_col, *h_rp, *h_col;
    int *part_lg, *part_raw, *part_h;
    SYMADDR(b_aggT, B_aggT);       SYMADDR(b_h1, B_h1);
    SYMADDR(b_agg1, B_agg1);
    SYMADDR(b_nodeH1, B_nodeH1);   SYMADDR(b_nodeAgg1, B_nodeAgg1);
    SYMADDR(b_aggN, B_aggN);       SYMADDR(b_aggN2, B_aggN2);
    SYMADDR(b_lt, B_lt);
    SYMADDR(b_xws, B_xws);         SYMADDR(b_xwn, B_xwn);
    SYMADDR(b_hn1, B_hn1);         SYMADDR(b_hn2, B_hn2);
    SYMADDR(b_q, B_q);             SYMADDR(b_k, B_k);
    SYMADDR(b_v, B_v);             SYMADDR(b_attn, B_attn);
    SYMADDR(b_wkp, B_wkp);         SYMADDR(b_wvp, B_wvp);
    SYMADDR(b_wtp, B_wtp);         SYMADDR(b_wtmp, B_wtmp);
    SYMADDR(lg_cnt, LG_cnt);       SYMADDR(lg_cur, LG_cur);
    SYMADDR(raw_cnt, RAW_cnt);     SYMADDR(raw_cur, RAW_cur);
    SYMADDR(hh_cnt, HH_cnt);       SYMADDR(hh_cur, HH_cur);
    SYMADDR(lg_rp, LG_rp);         SYMADDR(lg_col, LG_col);
    SYMADDR(raw_rp, RAW_rp);       SYMADDR(raw_col, RAW_col);
    SYMADDR(h_rp, H_rp);           SYMADDR(h_col, H_col);
    SYMADDR(part_lg, PART_LG);     SYMADDR(part_raw, PART_RAW);
    SYMADDR(part_h, PART_H);

    static cudaStream_t s1 = nullptr, s2 = nullptr;
    static cudaEvent_t evFork = nullptr, evH = nullptr, evRaw = nullptr, evQ = nullptr,
                       evW = nullptr, evWT = nullptr;
    if (s1 == nullptr) {
        cudaStreamCreateWithFlags(&s1, cudaStreamNonBlocking);
        cudaStreamCreateWithFlags(&s2, cudaStreamNonBlocking);
        cudaEventCreateWithFlags(&evFork, cudaEventDisableTiming);
        cudaEventCreateWithFlags(&evH, cudaEventDisableTiming);
        cudaEventCreateWithFlags(&evRaw, cudaEventDisableTiming);
        cudaEventCreateWithFlags(&evQ, cudaEventDisableTiming);
        cudaEventCreateWithFlags(&evW, cudaEventDisableTiming);
        cudaEventCreateWithFlags(&evWT, cudaEventDisableTiming);
    }

    const int TB = 256;
    const int gridE_gemm = (Ee + 127) / 128;
    const int gridN_gemm = (Nn + 127) / 128;
    const int gridE_row = (Ee + 7) / 8;
    const int gridN_row = (Nn + 7) / 8;
    const int npLG = (Ee + SCHUNK - 1) / SCHUNK;
    const int npN  = (Nn + SCHUNK - 1) / SCHUNK;

    // ======== fork ========
    cudaEventRecord(evFork, 0);
    cudaStreamWaitEvent(s1, evFork, 0);
    cudaStreamWaitEvent(s2, evFork, 0);

    // ======== s2: H incidence CSR, then folded-weight GEMMs (slack time) ========
    zero_int_k<<<(Nn + TB - 1) / TB, TB, 0, s2>>>(hh_cnt, Nn);
    hist_k<<<(2 * Ee + TB - 1) / TB, TB, 0, s2>>>(H, hh_cnt, 2 * Ee);
    chunksum_k<<<npN, 256, 0, s2>>>(hh_cnt, Nn, part_h);
    scanpart_k<<<1, 256, 0, s2>>>(part_h, npN, h_rp + Nn);
    chunkscan_k<<<npN, 256, 0, s2>>>(hh_cnt, Nn, part_h, h_rp, hh_cur);
    fill_eid2_k<<<(2 * Ee + TB - 1) / TB, TB, 0, s2>>>(H, hh_cur, h_col, Ee);
    cudaEventRecord(evH, s2);
    // Wtp = [W_tsa2_s@W_etn ; W_tsa2_n@W_etn]
    gemm_k<<<1, 256, 0, s2>>>(W_tsa2_s, HIDd, W_etn, nullptr, 0, nullptr, b_wtp, 128, 0);
    gemm_k<<<1, 256, 0, s2>>>(W_tsa2_n, HIDd, W_etn, nullptr, 0, nullptr, b_wtp + 128 * 128, 128, 0);
    cudaEventRecord(evWT, s2);
    // Wkp/Wvp = W_eg_lin @ (W_ea_{s,n} @ W{k,v})  (triple products)
    gemm_k<<<1, 256, 0, s2>>>(W_ea_s, HIDd, Wk, nullptr, 0, nullptr, b_wtmp, 128, 0);
    gemm_k<<<1, 256, 0, s2>>>(W_eg_lin, HIDd, b_wtmp, nullptr, 0, nullptr, b_wkp, 128, 0);
    gemm_k<<<1, 256, 0, s2>>>(W_ea_n, HIDd, Wk, nullptr, 0, nullptr, b_wtmp, 128, 0);
    gemm_k<<<1, 256, 0, s2>>>(W_eg_lin, HIDd, b_wtmp, nullptr, 0, nullptr, b_wkp + 128 * 128, 128, 0);
    gemm_k<<<1, 256, 0, s2>>>(W_ea_s, HIDd, Wv, nullptr, 0, nullptr, b_wtmp, 128, 0);
    gemm_k<<<1, 256, 0, s2>>>(W_eg_lin, HIDd, b_wtmp, nullptr, 0, nullptr, b_wvp, 128, 0);
    gemm_k<<<1, 256, 0, s2>>>(W_ea_n, HIDd, Wv, nullptr, 0, nullptr, b_wtmp, 128, 0);
    gemm_k<<<1, 256, 0, s2>>>(W_eg_lin, HIDd, b_wtmp, nullptr, 0, nullptr, b_wvp + 128 * 128, 128, 0);
    cudaEventRecord(evW, s2);

    // ======== s1: raw CSR + attr_node chain + q projection ========
    zero_int_k<<<(Nn + TB - 1) / TB, TB, 0, s1>>>(raw_cnt, Nn);
    hist_k<<<(Ee + TB - 1) / TB, TB, 0, s1>>>(rdst, raw_cnt, Ee);
    chunksum_k<<<npN, 256, 0, s1>>>(raw_cnt, Nn, part_raw);
    scanpart_k<<<1, 256, 0, s1>>>(part_raw, npN, raw_rp + Nn);
    chunkscan_k<<<npN, 256, 0, s1>>>(raw_cnt, Nn, part_raw, raw_rp, raw_cur);
    fill_src_k<<<(Ee + TB - 1) / TB, TB, 0, s1>>>(rdst, rsrc, raw_cur, raw_col, Ee);
    cudaEventRecord(evRaw, s1);
    gemm_k<<<gridN_gemm, 256, 0, s1>>>(x, FNODE, W_an1_s, nullptr, 0, nullptr, b_xws, Nn, 0);
    gemm_k<<<gridN_gemm, 256, 0, s1>>>(x, FNODE, W_an1_n, nullptr, 0, nullptr, b_xwn, Nn, 0);
    gather128x4_k<<<gridN_row, TB, 0, s1>>>(b_xwn, raw_rp, raw_col, b_hn1, b_xws, 1, Nn);
    gather128x4_k<<<gridN_row, TB, 0, s1>>>(b_hn1, raw_rp, raw_col, b_aggN2, nullptr, 0, Nn);
    gemm_k<<<gridN_gemm, 256, 0, s1>>>(b_hn1, HIDd, W_an2_s, b_aggN2, HIDd, W_an2_n, b_hn2, Nn, 0);
    gemm_k<<<gridN_gemm, 256, 0, s1>>>(b_hn2, HIDd, Wq, nullptr, 0, nullptr, b_q, Nn, 0);
    cudaEventRecord(evQ, s1);

    // ======== s0: line-graph CSR + TSA1 + LGE gather ========
    zero_int_k<<<(Ee + TB - 1) / TB, TB>>>(lg_cnt, Ee);
    hist_k<<<(LGEe + TB - 1) / TB, TB>>>(ldst, lg_cnt, LGEe);
    chunksum_k<<<npLG, 256>>>(lg_cnt, Ee, part_lg);
    scanpart_k<<<1, 256>>>(part_lg, npLG, lg_rp + Ee);
    chunkscan_k<<<npLG, 256>>>(lg_cnt, Ee, part_lg, lg_rp, lg_cur);
    fill_src_k<<<(LGEe + TB - 1) / TB, TB>>>(ldst, lsrc, lg_cur, lg_col, LGEe);

    gather64_k<<<gridE_row, TB>>>(et, lg_rp, lg_col, b_aggT, Ee);
    gemm_k<<<gridE_gemm, 256>>>(et, Tt, W_tsa1_s, b_aggT, Tt, W_tsa1_n, b_h1, Ee, 1);
    gather128_k<<<gridE_row, TB>>>(b_h1, lg_rp, lg_col, b_agg1, nullptr, 0, Ee);

    // ======== TSA2 + EdgeToNodeConv folded: gather h1/agg1 to node scale, N-GEMM ========
    cudaStreamWaitEvent(0, evH, 0);
    gatherH2_k<<<gridN_row, TB>>>(b_h1, b_agg1, h_rp, h_col, b_nodeH1, b_nodeAgg1, Nn);
    cudaStreamWaitEvent(0, evWT, 0);
    gemm_k<<<gridN_gemm, 256>>>(b_nodeH1, HIDd, b_wtp,
                                b_nodeAgg1, HIDd, b_wtp + 128 * 128, b_lt, Nn, 2 /*leaky*/);

    // join raw CSR; K/V from [lt, mean_raw(lt)] via triple-folded weights
    cudaStreamWaitEvent(0, evRaw, 0);
    cudaStreamWaitEvent(0, evW, 0);
    gather128x4_k<<<gridN_row, TB>>>(b_lt, raw_rp, raw_col, b_aggN, nullptr, 0, Nn);
    gemm_k<<<gridN_gemm, 256>>>(b_lt, HIDd, b_wkp,
                                b_aggN, HIDd, b_wkp + 128 * 128, b_k, Nn, 0);
    gemm_k<<<gridN_gemm, 256>>>(b_lt, HIDd, b_wvp,
                                b_aggN, HIDd, b_wvp + 128 * 128, b_v, Nn, 0);

    // join q/hn2, then single-pass online attention + classifier
    cudaStreamWaitEvent(0, evQ, 0);
    attn_online_k<<<gridN_row, TB>>>(b_q, b_k, b_v, raw_rp, raw_col, b_attn, Nn);
    final_k<<<(Nn + 7) / 8, 256>>>(b_hn2, b_attn, W_out, out);
}